// round 1
// baseline (speedup 1.0000x reference)
#include <cuda_runtime.h>

#define N_TRAJ 256
#define T_LEN  1024
#define K_TYPES 1000
#define D_EMB  64
#define EPS 1e-8f

// ---------------------------------------------------------------------------
// Kernel 1: per-trajectory fused reduction.
// One block per n (256 blocks, 256 threads). Each thread strides over T.
// Computes:
//   tm  = sum_t log(intensity + eps) * mask
//   ev  = sum_t log(prob_event[n,t,et[n,t]] + eps) * mask
// Writes:
//   out[n]        = (tm - Lambda[n]) + ev      (ll_N)
//   out[N+1+n]    = tm - Lambda[n]             (time_loglik_NT)
// ---------------------------------------------------------------------------
__global__ void traj_reduce_kernel(const int* __restrict__ event_types,
                                   const float* __restrict__ prob_event,
                                   const float* __restrict__ intensities,
                                   const float* __restrict__ Lambda,
                                   const float* __restrict__ input_mask,
                                   float* __restrict__ out) {
    const int n = blockIdx.x;
    const int tid = threadIdx.x;
    const int base = n * T_LEN;

    float ev = 0.0f;
    float tm = 0.0f;

    for (int t = tid; t < T_LEN; t += blockDim.x) {
        const float m   = input_mask[base + t];
        const float inz = intensities[base + t];
        tm = fmaf(__logf(inz + EPS), m, tm);

        const int e = event_types[base + t];
        const float p = __ldg(&prob_event[(long long)(base + t) * K_TYPES + e]);
        ev = fmaf(__logf(p + EPS), m, ev);
    }

    __shared__ float s_ev[256];
    __shared__ float s_tm[256];
    s_ev[tid] = ev;
    s_tm[tid] = tm;
    __syncthreads();

    for (int s = 128; s > 0; s >>= 1) {
        if (tid < s) {
            s_ev[tid] += s_ev[tid + s];
            s_tm[tid] += s_tm[tid + s];
        }
        __syncthreads();
    }

    if (tid == 0) {
        const float tnt = s_tm[0] - Lambda[n];
        out[n]              = tnt + s_ev[0];   // ll_N
        out[N_TRAJ + 1 + n] = tnt;             // time_loglik_NT
    }
}

// ---------------------------------------------------------------------------
// Kernel 2: deterministic scalar sum of ll_N -> out[N]  (time_loglik)
// ---------------------------------------------------------------------------
__global__ void scalar_sum_kernel(float* __restrict__ out) {
    __shared__ float s[256];
    const int tid = threadIdx.x;
    s[tid] = out[tid];
    __syncthreads();
    for (int st = 128; st > 0; st >>= 1) {
        if (tid < st) s[tid] += s[tid + st];
        __syncthreads();
    }
    if (tid == 0) out[N_TRAJ] = s[0];
}

// ---------------------------------------------------------------------------
// Kernel 3: embedding gather. One thread per output float (N*T*D = 16.7M).
// Output region starts at float offset 513 (not 16B-aligned) -> scalar stores.
// Writes are fully coalesced; type_table reads hit L2 (256 KB working set).
// ---------------------------------------------------------------------------
__global__ void emb_gather_kernel(const int* __restrict__ event_types,
                                  const float* __restrict__ type_table,
                                  float* __restrict__ out_emb) {
    const int idx = blockIdx.x * blockDim.x + threadIdx.x;   // < N*T*D = 2^24
    const int row = idx >> 6;        // (n*T + t)
    const int d   = idx & (D_EMB - 1);
    const int e   = __ldg(&event_types[row]);
    out_emb[idx] = __ldg(&type_table[e * D_EMB + d]);
}

extern "C" void kernel_launch(void* const* d_in, const int* in_sizes, int n_in,
                              void* d_out, int out_size) {
    const int*   event_types = (const int*)  d_in[0];   // (N, T) int32
    const float* prob_event  = (const float*)d_in[1];   // (N, T, K)
    const float* intensities = (const float*)d_in[2];   // (N, T)
    const float* Lambda      = (const float*)d_in[3];   // (N,)
    const float* input_mask  = (const float*)d_in[4];   // (N, T)
    const float* type_table  = (const float*)d_in[5];   // (K, D)

    float* out = (float*)d_out;

    // Layout: [ll_N (256)] [time_loglik (1)] [time_loglik_NT (256)] [type_emb (N*T*D)]
    float* out_emb = out + (N_TRAJ + 1 + N_TRAJ);

    traj_reduce_kernel<<<N_TRAJ, 256>>>(event_types, prob_event, intensities,
                                        Lambda, input_mask, out);
    scalar_sum_kernel<<<1, 256>>>(out);

    const int total = N_TRAJ * T_LEN * D_EMB;          // 16,777,216
    emb_gather_kernel<<<total / 256, 256>>>(event_types, type_table, out_emb);
}

// round 2
// speedup vs baseline: 1.8406x; 1.8406x over previous
#include <cuda_runtime.h>

#define N_TRAJ  256
#define T_LEN   1024
#define K_TYPES 1000
#define D_EMB   64
#define EPS     1e-8f

// emb work: N*T*D = 16,777,216 floats. Bulk is float4 stores at out_emb+3
// (16B-aligned), 4,194,303 float4s cover pos [3, 16777215); one edge thread
// handles head pos {0,1,2} and tail pos {16777215}.
#define EMB_TOTAL    (N_TRAJ * T_LEN * D_EMB)          // 16777216
#define EMB_BULK4    ((EMB_TOTAL - 4) / 4)             // 4194303
#define EMB_THREADS  (EMB_BULK4 + 1)                   // 4194304
#define EMB_BLOCKS   (EMB_THREADS / 256)               // 16384

// ---------------------------------------------------------------------------
// Fused kernel:
//   blocks [0, 256)          : per-trajectory reduction (latency-bound gather,
//                              scheduled first so it hides under emb writes)
//   blocks [256, 256+16384)  : embedding gather, float4 stores
// ---------------------------------------------------------------------------
__global__ void fused_kernel(const int* __restrict__ event_types,
                             const float* __restrict__ prob_event,
                             const float* __restrict__ intensities,
                             const float* __restrict__ Lambda,
                             const float* __restrict__ input_mask,
                             const float* __restrict__ type_table,
                             float* __restrict__ out,
                             float* __restrict__ out_emb) {
    const int tid = threadIdx.x;

    if (blockIdx.x < N_TRAJ) {
        // ---------------- reduction path ----------------
        const int n = blockIdx.x;
        const int base = n * T_LEN;

        // Batch the 4 scattered gathers up-front for MLP.
        float m[4], inz[4], p[4];
        #pragma unroll
        for (int i = 0; i < 4; i++) {
            const int t = base + tid + i * 256;
            m[i]   = input_mask[t];
            inz[i] = intensities[t];
            const int e = event_types[t];
            p[i] = __ldg(&prob_event[(long long)t * K_TYPES + e]);
        }

        float ev = 0.0f, tm = 0.0f;
        #pragma unroll
        for (int i = 0; i < 4; i++) {
            tm = fmaf(__logf(inz[i] + EPS), m[i], tm);
            ev = fmaf(__logf(p[i]   + EPS), m[i], ev);
        }

        __shared__ float s_ev[256];
        __shared__ float s_tm[256];
        s_ev[tid] = ev;
        s_tm[tid] = tm;
        __syncthreads();

        #pragma unroll
        for (int s = 128; s > 0; s >>= 1) {
            if (tid < s) {
                s_ev[tid] += s_ev[tid + s];
                s_tm[tid] += s_tm[tid + s];
            }
            __syncthreads();
        }

        if (tid == 0) {
            const float tnt = s_tm[0] - Lambda[n];
            out[n]              = tnt + s_ev[0];   // ll_N
            out[N_TRAJ + 1 + n] = tnt;             // time_loglik_NT
        }
        return;
    }

    // ---------------- embedding path ----------------
    const int tid4 = (blockIdx.x - N_TRAJ) * 256 + tid;

    if (tid4 < EMB_BULK4) {
        const int pos = 3 + 4 * tid4;              // [3, 16777215)
        const int row = pos >> 6;
        const int d   = pos & (D_EMB - 1);         // d ≡ 3 (mod 4), d ∈ {3,7,...,63}
        float4 v;
        if (d != 63) {
            // all 4 elements in the same row
            const int e = __ldg(&event_types[row]);
            const float* tp = type_table + e * D_EMB + d;
            v.x = __ldg(tp + 0);
            v.y = __ldg(tp + 1);
            v.z = __ldg(tp + 2);
            v.w = __ldg(tp + 3);
        } else {
            // straddles a row boundary: x from row, y/z/w from row+1 (d=0,1,2)
            const int e0 = __ldg(&event_types[row]);
            const int e1 = __ldg(&event_types[row + 1]);
            v.x = __ldg(&type_table[e0 * D_EMB + 63]);
            const float* tp = type_table + e1 * D_EMB;
            v.y = __ldg(tp + 0);
            v.z = __ldg(tp + 1);
            v.w = __ldg(tp + 2);
        }
        *reinterpret_cast<float4*>(out_emb + pos) = v;   // 16B-aligned
    } else {
        // edge thread: head pos 0,1,2 (row 0) and tail pos EMB_TOTAL-1
        const int e0 = __ldg(&event_types[0]);
        out_emb[0] = __ldg(&type_table[e0 * D_EMB + 0]);
        out_emb[1] = __ldg(&type_table[e0 * D_EMB + 1]);
        out_emb[2] = __ldg(&type_table[e0 * D_EMB + 2]);
        const int lrow = (EMB_TOTAL - 1) >> 6;
        const int el = __ldg(&event_types[lrow]);
        out_emb[EMB_TOTAL - 1] = __ldg(&type_table[el * D_EMB + (D_EMB - 1)]);
    }
}

// ---------------------------------------------------------------------------
// Deterministic scalar sum of ll_N -> out[N]  (time_loglik)
// ---------------------------------------------------------------------------
__global__ void scalar_sum_kernel(float* __restrict__ out) {
    __shared__ float s[256];
    const int tid = threadIdx.x;
    s[tid] = out[tid];
    __syncthreads();
    #pragma unroll
    for (int st = 128; st > 0; st >>= 1) {
        if (tid < st) s[tid] += s[tid + st];
        __syncthreads();
    }
    if (tid == 0) out[N_TRAJ] = s[0];
}

extern "C" void kernel_launch(void* const* d_in, const int* in_sizes, int n_in,
                              void* d_out, int out_size) {
    const int*   event_types = (const int*)  d_in[0];   // (N, T) int32
    const float* prob_event  = (const float*)d_in[1];   // (N, T, K)
    const float* intensities = (const float*)d_in[2];   // (N, T)
    const float* Lambda      = (const float*)d_in[3];   // (N,)
    const float* input_mask  = (const float*)d_in[4];   // (N, T)
    const float* type_table  = (const float*)d_in[5];   // (K, D)

    float* out = (float*)d_out;
    // Layout: [ll_N (256)] [time_loglik (1)] [time_loglik_NT (256)] [type_emb]
    float* out_emb = out + (N_TRAJ + 1 + N_TRAJ);

    fused_kernel<<<N_TRAJ + EMB_BLOCKS, 256>>>(event_types, prob_event,
                                               intensities, Lambda, input_mask,
                                               type_table, out, out_emb);
    scalar_sum_kernel<<<1, 256>>>(out);
}

// round 3
// speedup vs baseline: 2.1683x; 1.1780x over previous
#include <cuda_runtime.h>

#define N_TRAJ  256
#define T_LEN   1024
#define K_TYPES 1000
#define D_EMB   64
#define EPS     1e-8f

// emb work: N*T*D = 16,777,216 floats. Bulk is float4 stores at out_emb+3
// (16B-aligned): EMB_BULK4 float4s cover float pos [3, 16777215); head pos
// {0,1,2} and tail pos {16777215} are edge work.
#define EMB_TOTAL    (N_TRAJ * T_LEN * D_EMB)          // 16777216
#define EMB_BULK4    ((EMB_TOTAL - 4) / 4)             // 4194303
#define EMB_HALF     ((EMB_BULK4 + 1) / 2)             // 2097152
#define EMB_BLOCKS   (EMB_HALF / 256)                  // 8192

__device__ int g_reduce_ctr;   // zero-initialized; reset to 0 at end of each launch

// One float4 of the embedding output, with two ALIGNED float4 table reads.
// pos = 3 + 4*t4  ->  d = pos & 63 is ≡ 3 (mod 4).
__device__ __forceinline__ void emb_one(int t4,
                                        const int* __restrict__ event_types,
                                        const float* __restrict__ type_table,
                                        float* __restrict__ out_emb) {
    const int pos = 3 + 4 * t4;
    const int row = pos >> 6;
    const int d   = pos & (D_EMB - 1);            // 3,7,...,63

    const int e = __ldg(&event_types[row]);
    // lo covers table[e][d-3 .. d]  (16B aligned)
    const float4 lo = __ldg((const float4*)(type_table + e * D_EMB + (d - 3)));

    // hi covers table[.][d+1 .. d+4]; for d==63 it wraps to the next row.
    int e2  = e;
    int off = d + 1;
    if (d == D_EMB - 1) {                          // 1/16 of threads
        e2  = __ldg(&event_types[row + 1]);
        off = 0;
    }
    const float4 hi = __ldg((const float4*)(type_table + e2 * D_EMB + off));

    float4 v;
    v.x = lo.w; v.y = hi.x; v.z = hi.y; v.w = hi.z;
    *reinterpret_cast<float4*>(out_emb + pos) = v;
}

// ---------------------------------------------------------------------------
// Fused kernel:
//   blocks [0, 256)           : per-trajectory reduction; last-done block also
//                               computes the scalar sum (deterministic order).
//   blocks [256, 256+8192)    : embedding gather, 2 float4s per thread.
// ---------------------------------------------------------------------------
__global__ void fused_kernel(const int* __restrict__ event_types,
                             const float* __restrict__ prob_event,
                             const float* __restrict__ intensities,
                             const float* __restrict__ Lambda,
                             const float* __restrict__ input_mask,
                             const float* __restrict__ type_table,
                             float* __restrict__ out,
                             float* __restrict__ out_emb) {
    const int tid = threadIdx.x;

    if (blockIdx.x < N_TRAJ) {
        // ---------------- reduction path ----------------
        const int n = blockIdx.x;
        const int base = n * T_LEN;

        float m[4], inz[4], p[4];
        #pragma unroll
        for (int i = 0; i < 4; i++) {
            const int t = base + tid + i * 256;
            m[i]   = input_mask[t];
            inz[i] = intensities[t];
            const int e = event_types[t];
            p[i] = __ldg(&prob_event[(long long)t * K_TYPES + e]);
        }

        float ev = 0.0f, tm = 0.0f;
        #pragma unroll
        for (int i = 0; i < 4; i++) {
            tm = fmaf(__logf(inz[i] + EPS), m[i], tm);
            ev = fmaf(__logf(p[i]   + EPS), m[i], ev);
        }

        __shared__ float s_ev[256];
        __shared__ float s_tm[256];
        s_ev[tid] = ev;
        s_tm[tid] = tm;
        __syncthreads();

        #pragma unroll
        for (int s = 128; s > 0; s >>= 1) {
            if (tid < s) {
                s_ev[tid] += s_ev[tid + s];
                s_tm[tid] += s_tm[tid + s];
            }
            __syncthreads();
        }

        if (tid == 0) {
            const float tnt = s_tm[0] - Lambda[n];
            out[n]              = tnt + s_ev[0];   // ll_N
            out[N_TRAJ + 1 + n] = tnt;             // time_loglik_NT
        }

        // ----- deterministic fold of the scalar sum into the last block -----
        __threadfence();                            // release out[n] writes
        __shared__ int is_last;
        if (tid == 0) {
            const int v = atomicAdd(&g_reduce_ctr, 1);
            is_last = (v == N_TRAJ - 1);
        }
        __syncthreads();
        if (is_last) {
            __threadfence();                        // acquire other blocks' out[]
            s_ev[tid] = out[tid];
            __syncthreads();
            #pragma unroll
            for (int s = 128; s > 0; s >>= 1) {
                if (tid < s) s_ev[tid] += s_ev[tid + s];
                __syncthreads();
            }
            if (tid == 0) {
                out[N_TRAJ] = s_ev[0];              // time_loglik
                g_reduce_ctr = 0;                   // reset for next graph replay
            }
        }
        return;
    }

    // ---------------- embedding path ----------------
    const int i = (blockIdx.x - N_TRAJ) * 256 + tid;   // i < EMB_HALF

    emb_one(i, event_types, type_table, out_emb);
    if (i + EMB_HALF < EMB_BULK4)
        emb_one(i + EMB_HALF, event_types, type_table, out_emb);

    if (blockIdx.x == N_TRAJ && tid == 0) {
        // head pos 0,1,2 (row 0) and tail pos EMB_TOTAL-1
        const int e0 = __ldg(&event_types[0]);
        out_emb[0] = __ldg(&type_table[e0 * D_EMB + 0]);
        out_emb[1] = __ldg(&type_table[e0 * D_EMB + 1]);
        out_emb[2] = __ldg(&type_table[e0 * D_EMB + 2]);
        const int lrow = (EMB_TOTAL - 1) >> 6;
        const int el = __ldg(&event_types[lrow]);
        out_emb[EMB_TOTAL - 1] = __ldg(&type_table[el * D_EMB + (D_EMB - 1)]);
    }
}

extern "C" void kernel_launch(void* const* d_in, const int* in_sizes, int n_in,
                              void* d_out, int out_size) {
    const int*   event_types = (const int*)  d_in[0];   // (N, T) int32
    const float* prob_event  = (const float*)d_in[1];   // (N, T, K)
    const float* intensities = (const float*)d_in[2];   // (N, T)
    const float* Lambda      = (const float*)d_in[3];   // (N,)
    const float* input_mask  = (const float*)d_in[4];   // (N, T)
    const float* type_table  = (const float*)d_in[5];   // (K, D)

    float* out = (float*)d_out;
    // Layout: [ll_N (256)] [time_loglik (1)] [time_loglik_NT (256)] [type_emb]
    float* out_emb = out + (N_TRAJ + 1 + N_TRAJ);

    fused_kernel<<<N_TRAJ + EMB_BLOCKS, 256>>>(event_types, prob_event,
                                               intensities, Lambda, input_mask,
                                               type_table, out, out_emb);
}